// round 4
// baseline (speedup 1.0000x reference)
#include <cuda_runtime.h>
#include <cuda_bf16.h>
#include <math.h>
#include <stdint.h>

#define EMBED  2048
#define LATENT 512
#define BSZ    2
#define SEQ    2048
#define NH     16
#define HD     128

typedef __nv_bfloat16 bf16;

// Does this compilation pass have tcgen05 (arch-specific sm_103a/sm_100a)?
#if !defined(__CUDA_ARCH__) || defined(__CUDA_ARCH_FEAT_SM103_ALL) || \
    defined(__CUDA_ARCH_FEAT_SM100_ALL) || defined(__CUDA_ARCH_SPECIFIC__) || \
    defined(__CUDA_ARCH_FAMILY_SPECIFIC__)
#define USE_TC 1
#else
#define USE_TC 0
#endif

// ---------------- device scratch (allocation-free) ----------------
#define XN   (2LL*2048*2048)
#define LATN (2LL*2048*512)
#define KVN  (2LL*2048*4096)

__device__ bf16  g_x_hi[XN],    g_x_lo[XN];
__device__ bf16  g_qw_hi[EMBED*EMBED],   g_qw_lo[EMBED*EMBED];
__device__ bf16  g_kvdw_hi[LATENT*EMBED], g_kvdw_lo[LATENT*EMBED];
__device__ bf16  g_kvuw_hi[2*EMBED*LATENT], g_kvuw_lo[2*EMBED*LATENT];
__device__ bf16  g_ow_hi[EMBED*EMBED],   g_ow_lo[EMBED*EMBED];
__device__ bf16  g_q_hi[XN],    g_q_lo[XN];
__device__ bf16  g_lat_hi[LATN], g_lat_lo[LATN];
__device__ float g_kv[KVN];
__device__ bf16  g_k_hi[XN],    g_k_lo[XN];
__device__ bf16  g_vt_hi[XN],   g_vt_lo[XN];
__device__ bf16  g_att_hi[XN],  g_att_lo[XN];

// ---------------- common helpers ----------------
__device__ __forceinline__ uint32_t smem_u32(const void* p) {
    uint32_t a;
    asm("{ .reg .u64 t; cvta.to.shared.u64 t, %1; cvt.u32.u64 %0, t; }"
        : "=r"(a) : "l"(p));
    return a;
}
#define SWZ(x) ((x) ^ (((x) >> 3) & 0x70))

__device__ __forceinline__ void split2(float v, bf16& h, bf16& l) {
    h = __float2bfloat16(v);
    l = __float2bfloat16(v - __bfloat162float(h));
}

// generic tensor-core helpers (legal on every pass, incl. arch-specific)
__device__ __forceinline__ void cpasync16(uint32_t dst, const void* src) {
    asm volatile("cp.async.cg.shared.global [%0], [%1], 16;"
                 :: "r"(dst), "l"(src) : "memory");
}
__device__ __forceinline__ void ldsm_x4(uint32_t* r, uint32_t addr) {
    asm volatile("ldmatrix.sync.aligned.m8n8.x4.shared.b16 {%0,%1,%2,%3}, [%4];"
                 : "=r"(r[0]), "=r"(r[1]), "=r"(r[2]), "=r"(r[3]) : "r"(addr));
}
__device__ __forceinline__ void ldsm_x2(uint32_t* r, uint32_t addr) {
    asm volatile("ldmatrix.sync.aligned.m8n8.x2.shared.b16 {%0,%1}, [%2];"
                 : "=r"(r[0]), "=r"(r[1]) : "r"(addr));
}
__device__ __forceinline__ void mma16816(float* d, const uint32_t* a, const uint32_t* b) {
    asm volatile(
        "mma.sync.aligned.m16n8k16.row.col.f32.bf16.bf16.f32 "
        "{%0,%1,%2,%3}, {%4,%5,%6,%7}, {%8,%9}, {%0,%1,%2,%3};"
        : "+f"(d[0]), "+f"(d[1]), "+f"(d[2]), "+f"(d[3])
        : "r"(a[0]), "r"(a[1]), "r"(a[2]), "r"(a[3]), "r"(b[0]), "r"(b[1]));
}
__device__ __forceinline__ uint32_t packbf(bf16 a, bf16 b) {
    __nv_bfloat162 t;
    t.x = a; t.y = b;
    return *reinterpret_cast<uint32_t*>(&t);
}
__device__ __forceinline__ void packsplit(float a, float b, uint32_t& hi, uint32_t& lo) {
    bf16 ha, la, hb, lb;
    split2(a, ha, la);
    split2(b, hb, lb);
    hi = packbf(ha, hb);
    lo = packbf(la, lb);
}

#if USE_TC
// ---------------- tcgen05 helpers (arch-specific pass only) ----------------
__device__ __forceinline__ uint32_t elect1() {
    uint32_t p;
    asm volatile("{ .reg .pred p; elect.sync _|p, 0xFFFFFFFF; selp.b32 %0,1,0,p; }"
                 : "=r"(p));
    return p;
}
#define TC_ALLOC(sa, n) \
    asm volatile("tcgen05.alloc.cta_group::1.sync.aligned.shared::cta.b32 [%0], %1;" \
                 :: "r"(sa), "r"(n) : "memory")
#define TC_DEALLOC(t, n) \
    asm volatile("tcgen05.dealloc.cta_group::1.sync.aligned.b32 %0, %1;" :: "r"(t), "r"(n))
#define TC_COMMIT(mb) \
    asm volatile("tcgen05.commit.cta_group::1.mbarrier::arrive::one.shared::cluster.b64 [%0];" \
                 :: "r"(mb) : "memory")
#define TC_FENCE_AFTER()  asm volatile("tcgen05.fence::after_thread_sync;" ::: "memory")
#define TC_WAIT_LD()      asm volatile("tcgen05.wait::ld.sync.aligned;" ::: "memory")
#define MBAR_INIT(mb, c) \
    asm volatile("mbarrier.init.shared.b64 [%0], %1;" :: "r"(mb), "r"(c) : "memory")
#define MBAR_WAIT(mb, ph) do { \
    uint32_t _mb = (mb); uint32_t _ph = (ph); uint32_t _done; \
    asm volatile("{ .reg .pred p; mbarrier.try_wait.parity.acquire.cta.shared::cta.b64 p, [%1], %2; selp.b32 %0,1,0,p; }" \
        : "=r"(_done) : "r"(_mb), "r"(_ph) : "memory"); \
    if (!_done) { \
        asm volatile("{ .reg .pred P1; WL_%=: mbarrier.try_wait.parity.acquire.cta.shared::cta.b64 P1, [%0], %1, 0x989680; @P1 bra.uni WD_%=; bra.uni WL_%=; WD_%=: }" \
            :: "r"(_mb), "r"(_ph) : "memory"); \
    } } while (0)

__device__ __forceinline__ void mma_bf16_ss(uint32_t d, uint64_t a, uint64_t b,
                                            uint32_t idesc, uint32_t en) {
    asm volatile(
        "{ .reg .pred p; setp.ne.u32 p, %5, 0;\n\t"
        "tcgen05.mma.cta_group::1.kind::f16 [%0], %1, %2, %3, {%4,%4,%4,%4}, p; }"
        :: "r"(d), "l"(a), "l"(b), "r"(idesc), "r"(0u), "r"(en) : "memory");
}
__device__ __forceinline__ void tmem_ld32(uint32_t* r, uint32_t a) {
    asm volatile(
        "tcgen05.ld.sync.aligned.32x32b.x32.b32 "
        "{%0,%1,%2,%3,%4,%5,%6,%7,%8,%9,%10,%11,%12,%13,%14,%15,"
        "%16,%17,%18,%19,%20,%21,%22,%23,%24,%25,%26,%27,%28,%29,%30,%31}, [%32];"
        : "=r"(r[0]), "=r"(r[1]), "=r"(r[2]), "=r"(r[3]), "=r"(r[4]), "=r"(r[5]),
          "=r"(r[6]), "=r"(r[7]), "=r"(r[8]), "=r"(r[9]), "=r"(r[10]), "=r"(r[11]),
          "=r"(r[12]), "=r"(r[13]), "=r"(r[14]), "=r"(r[15]), "=r"(r[16]), "=r"(r[17]),
          "=r"(r[18]), "=r"(r[19]), "=r"(r[20]), "=r"(r[21]), "=r"(r[22]), "=r"(r[23]),
          "=r"(r[24]), "=r"(r[25]), "=r"(r[26]), "=r"(r[27]), "=r"(r[28]), "=r"(r[29]),
          "=r"(r[30]), "=r"(r[31])
        : "r"(a));
}
__device__ __forceinline__ uint64_t mkdesc(uint32_t addr) {
    const uint64_t base = (2ULL << 61) | (1ULL << 46) | (64ULL << 32) | (1ULL << 16);
    return base | ((uint64_t)(addr >> 4) & 0x3FFF);
}
#define IDESC 0x8200490u
#endif

// ---------------- split-bf16 GEMM (128x128 tile), dual backend ----------------
#define SMEM_TILES 1024
#define SMEM_BYTES (1024 + 2 * 65536)

template <int OUTM>
__global__ __launch_bounds__(256)
void tgemm(const bf16* __restrict__ Ahi, const bf16* __restrict__ Alo, int lda,
           const bf16* __restrict__ Bhi, const bf16* __restrict__ Blo, int ldb,
           const float* __restrict__ bias, float scale,
           float* __restrict__ Cf, bf16* __restrict__ Chi, bf16* __restrict__ Clo,
           int ldc, int K, int zdiv,
           long long sA0, long long sA1, long long sB0, long long sB1,
           long long sC0, long long sC1)
{
    extern __shared__ char smem[];
    const int tid = threadIdx.x;
    const int wid = tid >> 5, lid = tid & 31;
    const uint32_t sb = smem_u32(smem);

    const int z = blockIdx.z, z0 = z / zdiv, z1 = z % zdiv;
    const long long aoff = z0 * sA0 + z1 * sA1;
    const long long boff = z0 * sB0 + z1 * sB1;
    const long long coff = z0 * sC0 + z1 * sC1;

    const int bm = blockIdx.y * 128, bn = blockIdx.x * 128;

    const int seg = tid & 7;
    const int r0  = tid >> 3;
    const bf16* pAh = Ahi + aoff + (long long)(bm + r0) * lda + seg * 8;
    const bf16* pAl = Alo + aoff + (long long)(bm + r0) * lda + seg * 8;
    const bf16* pBh = Bhi + boff + (long long)(bn + r0) * ldb + seg * 8;
    const bf16* pBl = Blo + boff + (long long)(bn + r0) * ldb + seg * 8;

    const int KC = K >> 6;

#if USE_TC
    if (wid == 0) TC_ALLOC(sb, 128);
    if (tid == 0) { MBAR_INIT(sb + 8, 1); MBAR_INIT(sb + 16, 1); }
    __syncthreads();
    uint32_t tmem;
    asm volatile("ld.shared.b32 %0, [%1];" : "=r"(tmem) : "r"(sb));

    const uint32_t mb[2] = { sb + 8, sb + 16 };

    for (int kc = 0; kc < KC; kc++) {
        const int buf = kc & 1;
        const int kk = kc << 6;

        uint4 va[4], vb[4], vc[4], vd[4];
#pragma unroll
        for (int i = 0; i < 4; i++) {
            const long long ra = (long long)(i * 32) * lda + kk;
            const long long rb = (long long)(i * 32) * ldb + kk;
            va[i] = *reinterpret_cast<const uint4*>(pAh + ra);
            vb[i] = *reinterpret_cast<const uint4*>(pAl + ra);
            vc[i] = *reinterpret_cast<const uint4*>(pBh + rb);
            vd[i] = *reinterpret_cast<const uint4*>(pBl + rb);
        }

        const int u = kc >> 1;
        if (u >= 1) MBAR_WAIT(mb[buf], (u - 1) & 1);

        char* tb = smem + SMEM_TILES + buf * 65536;
#pragma unroll
        for (int i = 0; i < 4; i++) {
            const uint32_t sw = SWZ(((r0 + i * 32) << 7) + (seg << 4));
            *reinterpret_cast<uint4*>(tb + sw)         = va[i];
            *reinterpret_cast<uint4*>(tb + 16384 + sw) = vb[i];
            *reinterpret_cast<uint4*>(tb + 32768 + sw) = vc[i];
            *reinterpret_cast<uint4*>(tb + 49152 + sw) = vd[i];
        }
        asm volatile("fence.proxy.async.shared::cta;" ::: "memory");
        __syncthreads();

        if (wid == 0) {
            if (elect1()) {
                const uint32_t tbu = sb + SMEM_TILES + buf * 65536;
                const uint64_t dah = mkdesc(tbu);
                const uint64_t dal = mkdesc(tbu + 16384);
                const uint64_t dbh = mkdesc(tbu + 32768);
                const uint64_t dbl = mkdesc(tbu + 49152);
#pragma unroll
                for (int t = 0; t < 3; t++) {
                    const uint64_t da = (t == 2) ? dal : dah;
                    const uint64_t db = (t == 1) ? dbl : dbh;
#pragma unroll
                    for (int ks = 0; ks < 4; ks++) {
                        const uint32_t en = !(kc == 0 && t == 0 && ks == 0);
                        mma_bf16_ss(tmem, da + ks * 2, db + ks * 2, IDESC, en);
                    }
                }
                TC_COMMIT(mb[buf]);
            }
        }
    }

    MBAR_WAIT(mb[(KC - 1) & 1], ((KC - 1) >> 1) & 1);
    TC_FENCE_AFTER();

    if (tid < 128) {
        const long long m = bm + wid * 32 + lid;
#pragma unroll 1
        for (int cb = 0; cb < 4; cb++) {
            uint32_t r[32];
            tmem_ld32(r, tmem + cb * 32);
            TC_WAIT_LD();
            const int n0 = bn + cb * 32;
            if (OUTM == 0) {
                alignas(16) float o[32];
#pragma unroll
                for (int c = 0; c < 32; c++) {
                    float v = __uint_as_float(r[c]) * scale;
                    if (bias) v += bias[n0 + c];
                    o[c] = v;
                }
                float* cp = Cf + coff + m * ldc + n0;
#pragma unroll
                for (int q4 = 0; q4 < 8; q4++)
                    *reinterpret_cast<float4*>(cp + q4 * 4) =
                        *reinterpret_cast<const float4*>(o + q4 * 4);
            } else {
                alignas(16) bf16 hv[32], lv[32];
#pragma unroll
                for (int c = 0; c < 32; c++) {
                    float v = __uint_as_float(r[c]) * scale;
                    if (bias) v += bias[n0 + c];
                    split2(v, hv[c], lv[c]);
                }
                bf16* hp = Chi + coff + m * ldc + n0;
                bf16* lp = Clo + coff + m * ldc + n0;
#pragma unroll
                for (int q4 = 0; q4 < 4; q4++) {
                    *reinterpret_cast<uint4*>(hp + q4 * 8) =
                        *reinterpret_cast<const uint4*>(hv + q4 * 8);
                    *reinterpret_cast<uint4*>(lp + q4 * 8) =
                        *reinterpret_cast<const uint4*>(lv + q4 * 8);
                }
            }
        }
    }
    __syncthreads();
    if (wid == 0) TC_DEALLOC(tmem, 128);

#else  // ================= generic mma.sync fallback =================
    const int wm = (wid & 1) * 64;
    const int wn = (wid >> 1) * 32;

    float acc[4][4][4];
#pragma unroll
    for (int mi = 0; mi < 4; mi++)
#pragma unroll
        for (int ni = 0; ni < 4; ni++)
#pragma unroll
            for (int c = 0; c < 4; c++) acc[mi][ni][c] = 0.f;

    auto issue_chunk = [&](int kc) {
        const int buf = kc & 1;
        const int kk = kc << 6;
        const uint32_t tb = sb + SMEM_TILES + buf * 65536;
#pragma unroll
        for (int i = 0; i < 4; i++) {
            const uint32_t sw = SWZ(((r0 + i * 32) << 7) + (seg << 4));
            const long long ra = (long long)(i * 32) * lda + kk;
            const long long rb = (long long)(i * 32) * ldb + kk;
            cpasync16(tb + sw,         pAh + ra);
            cpasync16(tb + 16384 + sw, pAl + ra);
            cpasync16(tb + 32768 + sw, pBh + rb);
            cpasync16(tb + 49152 + sw, pBl + rb);
        }
        asm volatile("cp.async.commit_group;" ::: "memory");
    };

    issue_chunk(0);

    const int arow  = wm + (lid & 15);
    const uint32_t akb = (lid >> 4) * 16;
    const int brow  = wn + (lid & 7);
    const uint32_t bkb = ((lid >> 3) & 1) * 16;

    for (int kc = 0; kc < KC; kc++) {
        if (kc + 1 < KC) {
            issue_chunk(kc + 1);
            asm volatile("cp.async.wait_group 1;" ::: "memory");
        } else {
            asm volatile("cp.async.wait_group 0;" ::: "memory");
        }
        __syncthreads();

        const uint32_t tb = sb + SMEM_TILES + (kc & 1) * 65536;
#pragma unroll
        for (int ks = 0; ks < 4; ks++) {
            uint32_t ah[4][4], al[4][4], bh[4][2], bl[4][2];
#pragma unroll
            for (int mi = 0; mi < 4; mi++) {
                const uint32_t off = SWZ((uint32_t)((arow + mi * 16) << 7) + ks * 32 + akb);
                ldsm_x4(ah[mi], tb + off);
                ldsm_x4(al[mi], tb + 16384 + off);
            }
#pragma unroll
            for (int ni = 0; ni < 4; ni++) {
                const uint32_t off = SWZ((uint32_t)((brow + ni * 8) << 7) + ks * 32 + bkb);
                ldsm_x2(bh[ni], tb + 32768 + off);
                ldsm_x2(bl[ni], tb + 49152 + off);
            }
#pragma unroll
            for (int mi = 0; mi < 4; mi++)
#pragma unroll
                for (int ni = 0; ni < 4; ni++) {
                    mma16816(acc[mi][ni], ah[mi], bh[ni]);
                    mma16816(acc[mi][ni], ah[mi], bl[ni]);
                    mma16816(acc[mi][ni], al[mi], bh[ni]);
                }
        }
        __syncthreads();
    }

    const int lr  = lid >> 2;
    const int lc2 = (lid & 3) * 2;
#pragma unroll
    for (int mi = 0; mi < 4; mi++) {
        const long long m0 = bm + wm + mi * 16 + lr;
#pragma unroll
        for (int ni = 0; ni < 4; ni++) {
            const int col = bn + wn + ni * 8 + lc2;
            const float b0 = bias ? bias[col] : 0.f;
            const float b1 = bias ? bias[col + 1] : 0.f;
            const float v00 = acc[mi][ni][0] * scale + b0;
            const float v01 = acc[mi][ni][1] * scale + b1;
            const float v10 = acc[mi][ni][2] * scale + b0;
            const float v11 = acc[mi][ni][3] * scale + b1;
            if (OUTM == 0) {
                *reinterpret_cast<float2*>(Cf + coff + m0 * ldc + col) =
                    make_float2(v00, v01);
                *reinterpret_cast<float2*>(Cf + coff + (m0 + 8) * ldc + col) =
                    make_float2(v10, v11);
            } else {
                uint32_t h0, l0, h1, l1;
                packsplit(v00, v01, h0, l0);
                packsplit(v10, v11, h1, l1);
                *reinterpret_cast<uint32_t*>(Chi + coff + m0 * ldc + col) = h0;
                *reinterpret_cast<uint32_t*>(Clo + coff + m0 * ldc + col) = l0;
                *reinterpret_cast<uint32_t*>(Chi + coff + (m0 + 8) * ldc + col) = h1;
                *reinterpret_cast<uint32_t*>(Clo + coff + (m0 + 8) * ldc + col) = l1;
            }
        }
    }
#endif
}

// ---------------- fused flash attention (generic mma.sync, runs on any pass) ----
// grid (SEQ/128, BSZ*NH), 256 threads. Q tile 128 rows in smem; K/V (hi,lo)
// tiles double-buffered via cp.async. S = 3-term split QK^T, online softmax,
// O += 3-term P*V^T with register repack. Writes att hi/lo planes.
#define FL_SMEM (3 * 65536)

__device__ __forceinline__ void fl_load_tile(uint32_t sm, const bf16* gh,
                                             const bf16* gl, int tid)
{
    const int r = tid >> 3, seg = tid & 7;
#pragma unroll
    for (int i = 0; i < 4; i++) {
        const int row = r + i * 32;
        const uint32_t sw = SWZ((row << 7) + (seg << 4));
        const long long go = (long long)row * 2048 + seg * 8;
        cpasync16(sm + sw,         gh + go);
        cpasync16(sm + 16384 + sw, gh + go + 64);
        cpasync16(sm + 32768 + sw, gl + go);
        cpasync16(sm + 49152 + sw, gl + go + 64);
    }
}

__global__ __launch_bounds__(256, 1)
void flash_kernel(const bf16* __restrict__ Qhi, const bf16* __restrict__ Qlo,
                  const bf16* __restrict__ Khi, const bf16* __restrict__ Klo,
                  const bf16* __restrict__ Vthi, const bf16* __restrict__ Vtlo,
                  bf16* __restrict__ Ahi, bf16* __restrict__ Alo)
{
    extern __shared__ char smem[];
    const uint32_t sb = smem_u32(smem);
    const uint32_t sQ = sb, sK = sb + 65536, sV = sb + 131072;

    const int tid = threadIdx.x;
    const int wid = tid >> 5, lid = tid & 31;
    const int bh = blockIdx.y, b = bh >> 4, h = bh & 15;
    const int q0 = blockIdx.x * 128;

    const bf16* qh = Qhi + (long long)(b * SEQ + q0) * 2048 + h * 128;
    const bf16* ql = Qlo + (long long)(b * SEQ + q0) * 2048 + h * 128;
    const bf16* kh = Khi + (long long)(b * SEQ) * 2048 + h * 128;
    const bf16* kl = Klo + (long long)(b * SEQ) * 2048 + h * 128;
    const bf16* vh = Vthi + (long long)bh * 128 * 2048;
    const bf16* vl = Vtlo + (long long)bh * 128 * 2048;

    fl_load_tile(sQ, qh, ql, tid);
    asm volatile("cp.async.commit_group;" ::: "memory");
    fl_load_tile(sK, kh, kl, tid);
    asm volatile("cp.async.commit_group;" ::: "memory");
    fl_load_tile(sV, vh, vl, tid);
    asm volatile("cp.async.commit_group;" ::: "memory");

    float o[16][4];
#pragma unroll
    for (int t = 0; t < 16; t++)
#pragma unroll
        for (int c = 0; c < 4; c++) o[t][c] = 0.f;
    float m0 = -1e30f, m1 = -1e30f, l0 = 0.f, l1 = 0.f;

    // exp2-domain scale: log2(e)/sqrt(HD)
    const float SC = 1.4426950408889634f * 0.08838834764831845f;

    const int arow = wid * 16 + (lid & 15);
    const uint32_t akb = (lid >> 4) * 16;
    const int brow8 = lid & 7;
    const uint32_t bkb = ((lid >> 3) & 1) * 16;

    for (int j = 0; j < 16; j++) {
        asm volatile("cp.async.wait_group 1;" ::: "memory");  // K_j (and Q) ready
        __syncthreads();

        // ---- S = Q K^T (3-term) ----
        float s[16][4];
#pragma unroll
        for (int t = 0; t < 16; t++)
#pragma unroll
            for (int c = 0; c < 4; c++) s[t][c] = 0.f;

#pragma unroll 1
        for (int ks = 0; ks < 8; ks++) {
            const uint32_t qoff = SWZ((arow << 7) + (ks & 3) * 32 + akb) + (ks >> 2) * 16384;
            uint32_t qfh[4], qfl[4];
            ldsm_x4(qfh, sQ + qoff);
            ldsm_x4(qfl, sQ + 32768 + qoff);
#pragma unroll
            for (int nt = 0; nt < 16; nt++) {
                const uint32_t koff =
                    SWZ(((nt * 8 + brow8) << 7) + (ks & 3) * 32 + bkb) + (ks >> 2) * 16384;
                uint32_t kfh[2], kfl[2];
                ldsm_x2(kfh, sK + koff);
                ldsm_x2(kfl, sK + 32768 + koff);
                mma16816(s[nt], qfh, kfh);
                mma16816(s[nt], qfh, kfl);
                mma16816(s[nt], qfl, kfh);
            }
        }

        // ---- online softmax ----
        float tm0 = -1e30f, tm1 = -1e30f;
#pragma unroll
        for (int t = 0; t < 16; t++) {
            s[t][0] *= SC; s[t][1] *= SC; s[t][2] *= SC; s[t][3] *= SC;
            tm0 = fmaxf(tm0, fmaxf(s[t][0], s[t][1]));
            tm1 = fmaxf(tm1, fmaxf(s[t][2], s[t][3]));
        }
        tm0 = fmaxf(tm0, __shfl_xor_sync(0xffffffff, tm0, 1));
        tm0 = fmaxf(tm0, __shfl_xor_sync(0xffffffff, tm0, 2));
        tm1 = fmaxf(tm1, __shfl_xor_sync(0xffffffff, tm1, 1));
        tm1 = fmaxf(tm1, __shfl_xor_sync(0xffffffff, tm1, 2));
        const float mn0 = fmaxf(m0, tm0), mn1 = fmaxf(m1, tm1);
        const float sc0 = exp2f(m0 - mn0), sc1 = exp2f(m1 - mn1);
        m0 = mn0; m1 = mn1;

        float ts0 = 0.f, ts1 = 0.f;
#pragma unroll
        for (int t = 0; t < 16; t++) {
            s[t][0] = exp2f(s[t][0] - m0);
            s[t][1] = exp2f(s[t][1] - m0);
            s[t][2] = exp2f(s[t][2] - m1);
            s[t][3] = exp2f(s[t][3] - m1);
            ts0 += s[t][0] + s[t][1];
            ts1 += s[t][2] + s[t][3];
            o[t][0] *= sc0; o[t][1] *= sc0;
            o[t][2] *= sc1; o[t][3] *= sc1;
        }
        l0 = l0 * sc0 + ts0;
        l1 = l1 * sc1 + ts1;

        // ---- done reading K buffer; prefetch K_{j+1} ----
        __syncthreads();
        if (j + 1 < 16)
            fl_load_tile(sK, kh + (long long)(j + 1) * 128 * 2048,
                         kl + (long long)(j + 1) * 128 * 2048, tid);
        asm volatile("cp.async.commit_group;" ::: "memory");

        asm volatile("cp.async.wait_group 1;" ::: "memory");  // V_j ready
        __syncthreads();

        // ---- O += P V^T (3-term, P repacked in registers) ----
#pragma unroll 1
        for (int ks = 0; ks < 8; ks++) {
            uint32_t ph[4], pl[4];
            packsplit(s[2 * ks][0],     s[2 * ks][1],     ph[0], pl[0]);
            packsplit(s[2 * ks][2],     s[2 * ks][3],     ph[1], pl[1]);
            packsplit(s[2 * ks + 1][0], s[2 * ks + 1][1], ph[2], pl[2]);
            packsplit(s[2 * ks + 1][2], s[2 * ks + 1][3], ph[3], pl[3]);
#pragma unroll
            for (int nt = 0; nt < 16; nt++) {
                const uint32_t voff =
                    SWZ(((nt * 8 + brow8) << 7) + (ks & 3) * 32 + bkb) + (ks >> 2) * 16384;
                uint32_t vfh[2], vfl[2];
                ldsm_x2(vfh, sV + voff);
                ldsm_x2(vfl, sV + 32768 + voff);
                mma16816(o[nt], ph, vfh);
                mma16816(o[nt], ph, vfl);
                mma16816(o[nt], pl, vfh);
            }
        }

        // ---- done reading V buffer; prefetch V_{j+1} ----
        __syncthreads();
        if (j + 1 < 16)
            fl_load_tile(sV, vh + (j + 1) * 128, vl + (j + 1) * 128, tid);
        asm volatile("cp.async.commit_group;" ::: "memory");
    }

    // ---- epilogue: normalize and write att hi/lo ----
    l0 += __shfl_xor_sync(0xffffffff, l0, 1);
    l0 += __shfl_xor_sync(0xffffffff, l0, 2);
    l1 += __shfl_xor_sync(0xffffffff, l1, 1);
    l1 += __shfl_xor_sync(0xffffffff, l1, 2);
    const float inv0 = 1.f / l0, inv1 = 1.f / l1;

    const int g = lid >> 2;
    const long long row0 = (long long)(b * SEQ + q0 + wid * 16 + g);
    const long long row1 = row0 + 8;
    const int colb = h * 128 + (lid & 3) * 2;
#pragma unroll
    for (int nt = 0; nt < 16; nt++) {
        const int col = colb + nt * 8;
        uint32_t h0, lo0, h1, lo1;
        packsplit(o[nt][0] * inv0, o[nt][1] * inv0, h0, lo0);
        packsplit(o[nt][2] * inv1, o[nt][3] * inv1, h1, lo1);
        *reinterpret_cast<uint32_t*>(Ahi + row0 * 2048 + col) = h0;
        *reinterpret_cast<uint32_t*>(Alo + row0 * 2048 + col) = lo0;
        *reinterpret_cast<uint32_t*>(Ahi + row1 * 2048 + col) = h1;
        *reinterpret_cast<uint32_t*>(Alo + row1 * 2048 + col) = lo1;
    }
}

// ---------------- elementwise split kernels ----------------
__global__ void split_kernel(const float* __restrict__ in,
                             bf16* __restrict__ hi, bf16* __restrict__ lo,
                             long long n)
{
    const long long i = ((long long)blockIdx.x * blockDim.x + threadIdx.x) * 4;
    if (i >= n) return;
    const float4 v = *reinterpret_cast<const float4*>(in + i);
    alignas(8) bf16 h[4], l[4];
    split2(v.x, h[0], l[0]); split2(v.y, h[1], l[1]);
    split2(v.z, h[2], l[2]); split2(v.w, h[3], l[3]);
    *reinterpret_cast<uint2*>(hi + i) = *reinterpret_cast<const uint2*>(h);
    *reinterpret_cast<uint2*>(lo + i) = *reinterpret_cast<const uint2*>(l);
}

__global__ void ksplit_kernel(const float* __restrict__ kv,
                              bf16* __restrict__ khi, bf16* __restrict__ klo)
{
    const long long i = ((long long)blockIdx.x * blockDim.x + threadIdx.x) * 4;
    if (i >= XN) return;
    const long long row = i >> 11, col = i & 2047;
    const float4 v = *reinterpret_cast<const float4*>(kv + row * 4096 + col);
    alignas(8) bf16 h[4], l[4];
    split2(v.x, h[0], l[0]); split2(v.y, h[1], l[1]);
    split2(v.z, h[2], l[2]); split2(v.w, h[3], l[3]);
    *reinterpret_cast<uint2*>(khi + i) = *reinterpret_cast<const uint2*>(h);
    *reinterpret_cast<uint2*>(klo + i) = *reinterpret_cast<const uint2*>(l);
}

__global__ void vtrans_kernel(const float* __restrict__ kv,
                              bf16* __restrict__ vthi, bf16* __restrict__ vtlo)
{
    __shared__ float t[32][33];
    const int b = blockIdx.z >> 4, h = blockIdx.z & 15;
    const int s0 = blockIdx.x * 32, d0 = blockIdx.y * 32;
    const int tx = threadIdx.x, ty = threadIdx.y;
    t[ty][tx] = kv[(long long)(b * SEQ + s0 + ty) * 4096 + 2048 + h * 128 + d0 + tx];
    __syncthreads();
    const float v = t[tx][ty];
    const long long o = (long long)((b * NH + h) * HD + d0 + ty) * SEQ + s0 + tx;
    bf16 hv, lv;
    split2(v, hv, lv);
    vthi[o] = hv;
    vtlo[o] = lv;
}

// ---------------- host ----------------
static void do_split(const float* in, bf16* hi, bf16* lo, long long n) {
    split_kernel<<<(unsigned)((n / 4 + 255) / 256), 256>>>(in, hi, lo, n);
}

extern "C" void kernel_launch(void* const* d_in, const int* in_sizes, int n_in,
                              void* d_out, int out_size)
{
    const float* x     = (const float*)d_in[0];
    const float* q_w   = (const float*)d_in[1];
    const float* q_b   = (const float*)d_in[2];
    const float* kvd_w = (const float*)d_in[3];
    const float* kvd_b = (const float*)d_in[4];
    const float* kvu_w = (const float*)d_in[5];
    const float* kvu_b = (const float*)d_in[6];
    const float* out_w = (const float*)d_in[7];
    const float* out_b = (const float*)d_in[8];
    float* out = (float*)d_out;

    bf16 *x_hi, *x_lo, *qw_hi, *qw_lo, *kvdw_hi, *kvdw_lo, *kvuw_hi, *kvuw_lo,
         *ow_hi, *ow_lo, *q_hi, *q_lo, *lat_hi, *lat_lo, *k_hi, *k_lo,
         *vt_hi, *vt_lo, *att_hi, *att_lo;
    float *kv;
    cudaGetSymbolAddress((void**)&x_hi, g_x_hi);     cudaGetSymbolAddress((void**)&x_lo, g_x_lo);
    cudaGetSymbolAddress((void**)&qw_hi, g_qw_hi);   cudaGetSymbolAddress((void**)&qw_lo, g_qw_lo);
    cudaGetSymbolAddress((void**)&kvdw_hi, g_kvdw_hi); cudaGetSymbolAddress((void**)&kvdw_lo, g_kvdw_lo);
    cudaGetSymbolAddress((void**)&kvuw_hi, g_kvuw_hi); cudaGetSymbolAddress((void**)&kvuw_lo, g_kvuw_lo);
    cudaGetSymbolAddress((void**)&ow_hi, g_ow_hi);   cudaGetSymbolAddress((void**)&ow_lo, g_ow_lo);
    cudaGetSymbolAddress((void**)&q_hi, g_q_hi);     cudaGetSymbolAddress((void**)&q_lo, g_q_lo);
    cudaGetSymbolAddress((void**)&lat_hi, g_lat_hi); cudaGetSymbolAddress((void**)&lat_lo, g_lat_lo);
    cudaGetSymbolAddress((void**)&k_hi, g_k_hi);     cudaGetSymbolAddress((void**)&k_lo, g_k_lo);
    cudaGetSymbolAddress((void**)&vt_hi, g_vt_hi);   cudaGetSymbolAddress((void**)&vt_lo, g_vt_lo);
    cudaGetSymbolAddress((void**)&att_hi, g_att_hi); cudaGetSymbolAddress((void**)&att_lo, g_att_lo);
    cudaGetSymbolAddress((void**)&kv, g_kv);

    cudaFuncSetAttribute(tgemm<0>, cudaFuncAttributeMaxDynamicSharedMemorySize, SMEM_BYTES);
    cudaFuncSetAttribute(tgemm<1>, cudaFuncAttributeMaxDynamicSharedMemorySize, SMEM_BYTES);
    cudaFuncSetAttribute(flash_kernel, cudaFuncAttributeMaxDynamicSharedMemorySize, FL_SMEM);

    do_split(x,     x_hi,    x_lo,    XN);
    do_split(q_w,   qw_hi,   qw_lo,   (long long)EMBED * EMBED);
    do_split(kvd_w, kvdw_hi, kvdw_lo, (long long)LATENT * EMBED);
    do_split(kvu_w, kvuw_hi, kvuw_lo, (long long)2 * EMBED * LATENT);
    do_split(out_w, ow_hi,   ow_lo,   (long long)EMBED * EMBED);

    const int M = BSZ * SEQ;  // 4096

    // 1) q = x @ q_w^T + q_b -> hi/lo planes
    tgemm<1><<<dim3(EMBED / 128, M / 128, 1), 256, SMEM_BYTES>>>(
        x_hi, x_lo, EMBED, qw_hi, qw_lo, EMBED, q_b, 1.f,
        nullptr, q_hi, q_lo, EMBED, EMBED, 1, 0, 0, 0, 0, 0, 0);

    // 2) latent = x @ kvd_w^T + kvd_b -> hi/lo
    tgemm<1><<<dim3(LATENT / 128, M / 128, 1), 256, SMEM_BYTES>>>(
        x_hi, x_lo, EMBED, kvdw_hi, kvdw_lo, EMBED, kvd_b, 1.f,
        nullptr, lat_hi, lat_lo, LATENT, EMBED, 1, 0, 0, 0, 0, 0, 0);

    // 3) kv = latent @ kvu_w^T + kvu_b -> fp32
    tgemm<0><<<dim3(2 * EMBED / 128, M / 128, 1), 256, SMEM_BYTES>>>(
        lat_hi, lat_lo, LATENT, kvuw_hi, kvuw_lo, LATENT, kvu_b, 1.f,
        kv, nullptr, nullptr, 2 * EMBED, LATENT, 1, 0, 0, 0, 0, 0, 0);

    // 4) k split + v transpose-split
    ksplit_kernel<<<(unsigned)(XN / 4 / 256), 256>>>(kv, k_hi, k_lo);
    vtrans_kernel<<<dim3(SEQ / 32, HD / 32, BSZ * NH), dim3(32, 32)>>>(kv, vt_hi, vt_lo);

    // 5-7) fused flash attention -> att hi/lo
    flash_kernel<<<dim3(SEQ / 128, BSZ * NH), 256, FL_SMEM>>>(
        q_hi, q_lo, k_hi, k_lo, vt_hi, vt_lo, att_hi, att_lo);

    // 8) out = att @ out_w^T + out_b -> fp32 (d_out)
    tgemm<0><<<dim3(EMBED / 128, M / 128, 1), 256, SMEM_BYTES>>>(
        att_hi, att_lo, EMBED, ow_hi, ow_lo, EMBED, out_b, 1.f,
        out, nullptr, nullptr, EMBED, EMBED, 1, 0, 0, 0, 0, 0, 0);
}

// round 5
// speedup vs baseline: 1.1431x; 1.1431x over previous
#include <cuda_runtime.h>
#include <cuda_bf16.h>
#include <math.h>
#include <stdint.h>

#define EMBED  2048
#define LATENT 512
#define BSZ    2
#define SEQ    2048
#define NH     16
#define HD     128

typedef __nv_bfloat16 bf16;

// ---------------- device scratch (allocation-free) ----------------
#define XN   (2LL*2048*2048)
#define LATN (2LL*2048*512)
#define KVN  (2LL*2048*4096)

__device__ bf16  g_x_hi[XN],    g_x_lo[XN];
__device__ bf16  g_qw_hi[EMBED*EMBED],   g_qw_lo[EMBED*EMBED];
__device__ bf16  g_kvdw_hi[LATENT*EMBED], g_kvdw_lo[LATENT*EMBED];
__device__ bf16  g_kvuw_hi[2*EMBED*LATENT], g_kvuw_lo[2*EMBED*LATENT];
__device__ bf16  g_ow_hi[EMBED*EMBED],   g_ow_lo[EMBED*EMBED];
__device__ bf16  g_q_hi[XN],    g_q_lo[XN];
__device__ bf16  g_lat_hi[LATN], g_lat_lo[LATN];
__device__ float g_kv[KVN];
__device__ bf16  g_k_hi[XN],    g_k_lo[XN];
__device__ bf16  g_vt_hi[XN],   g_vt_lo[XN];
__device__ bf16  g_att_hi[XN],  g_att_lo[XN];

// ---------------- common helpers ----------------
__device__ __forceinline__ uint32_t smem_u32(const void* p) {
    uint32_t a;
    asm("{ .reg .u64 t; cvta.to.shared.u64 t, %1; cvt.u32.u64 %0, t; }"
        : "=r"(a) : "l"(p));
    return a;
}
#define SWZ(x) ((x) ^ (((x) >> 3) & 0x70))

__device__ __forceinline__ void split2(float v, bf16& h, bf16& l) {
    h = __float2bfloat16(v);
    l = __float2bfloat16(v - __bfloat162float(h));
}

__device__ __forceinline__ void cpasync16(uint32_t dst, const void* src) {
    asm volatile("cp.async.cg.shared.global [%0], [%1], 16;"
                 :: "r"(dst), "l"(src) : "memory");
}
__device__ __forceinline__ void ldsm_x4(uint32_t* r, uint32_t addr) {
    asm volatile("ldmatrix.sync.aligned.m8n8.x4.shared.b16 {%0,%1,%2,%3}, [%4];"
                 : "=r"(r[0]), "=r"(r[1]), "=r"(r[2]), "=r"(r[3]) : "r"(addr));
}
__device__ __forceinline__ void ldsm_x2(uint32_t* r, uint32_t addr) {
    asm volatile("ldmatrix.sync.aligned.m8n8.x2.shared.b16 {%0,%1}, [%2];"
                 : "=r"(r[0]), "=r"(r[1]) : "r"(addr));
}
__device__ __forceinline__ void mma16816(float* d, const uint32_t* a, const uint32_t* b) {
    asm volatile(
        "mma.sync.aligned.m16n8k16.row.col.f32.bf16.bf16.f32 "
        "{%0,%1,%2,%3}, {%4,%5,%6,%7}, {%8,%9}, {%0,%1,%2,%3};"
        : "+f"(d[0]), "+f"(d[1]), "+f"(d[2]), "+f"(d[3])
        : "r"(a[0]), "r"(a[1]), "r"(a[2]), "r"(a[3]), "r"(b[0]), "r"(b[1]));
}
__device__ __forceinline__ uint32_t packbf(bf16 a, bf16 b) {
    __nv_bfloat162 t;
    t.x = a; t.y = b;
    return *reinterpret_cast<uint32_t*>(&t);
}
__device__ __forceinline__ void packsplit(float a, float b, uint32_t& hi, uint32_t& lo) {
    bf16 ha, la, hb, lb;
    split2(a, ha, la);
    split2(b, hb, lb);
    hi = packbf(ha, hb);
    lo = packbf(la, lb);
}

// ---------------- split-bf16 GEMM (128x128 tile), mma.sync ----------------
#define SMEM_TILES 1024
#define SMEM_BYTES (1024 + 2 * 65536)

template <int OUTM>
__global__ __launch_bounds__(256)
void tgemm(const bf16* __restrict__ Ahi, const bf16* __restrict__ Alo, int lda,
           const bf16* __restrict__ Bhi, const bf16* __restrict__ Blo, int ldb,
           const float* __restrict__ bias, float scale,
           float* __restrict__ Cf, bf16* __restrict__ Chi, bf16* __restrict__ Clo,
           int ldc, int K, int zdiv,
           long long sA0, long long sA1, long long sB0, long long sB1,
           long long sC0, long long sC1)
{
    extern __shared__ char smem[];
    const int tid = threadIdx.x;
    const int wid = tid >> 5, lid = tid & 31;
    const uint32_t sb = smem_u32(smem);

    const int z = blockIdx.z, z0 = z / zdiv, z1 = z % zdiv;
    const long long aoff = z0 * sA0 + z1 * sA1;
    const long long boff = z0 * sB0 + z1 * sB1;
    const long long coff = z0 * sC0 + z1 * sC1;

    const int bm = blockIdx.y * 128, bn = blockIdx.x * 128;

    const int seg = tid & 7;
    const int r0  = tid >> 3;
    const bf16* pAh = Ahi + aoff + (long long)(bm + r0) * lda + seg * 8;
    const bf16* pAl = Alo + aoff + (long long)(bm + r0) * lda + seg * 8;
    const bf16* pBh = Bhi + boff + (long long)(bn + r0) * ldb + seg * 8;
    const bf16* pBl = Blo + boff + (long long)(bn + r0) * ldb + seg * 8;

    const int KC = K >> 6;

    const int wm = (wid & 1) * 64;
    const int wn = (wid >> 1) * 32;

    float acc[4][4][4];
#pragma unroll
    for (int mi = 0; mi < 4; mi++)
#pragma unroll
        for (int ni = 0; ni < 4; ni++)
#pragma unroll
            for (int c = 0; c < 4; c++) acc[mi][ni][c] = 0.f;

    auto issue_chunk = [&](int kc) {
        const int buf = kc & 1;
        const int kk = kc << 6;
        const uint32_t tb = sb + SMEM_TILES + buf * 65536;
#pragma unroll
        for (int i = 0; i < 4; i++) {
            const uint32_t sw = SWZ(((r0 + i * 32) << 7) + (seg << 4));
            const long long ra = (long long)(i * 32) * lda + kk;
            const long long rb = (long long)(i * 32) * ldb + kk;
            cpasync16(tb + sw,         pAh + ra);
            cpasync16(tb + 16384 + sw, pAl + ra);
            cpasync16(tb + 32768 + sw, pBh + rb);
            cpasync16(tb + 49152 + sw, pBl + rb);
        }
        asm volatile("cp.async.commit_group;" ::: "memory");
    };

    issue_chunk(0);

    const int arow  = wm + (lid & 15);
    const uint32_t akb = (lid >> 4) * 16;
    const int brow  = wn + (lid & 7);
    const uint32_t bkb = ((lid >> 3) & 1) * 16;

    for (int kc = 0; kc < KC; kc++) {
        if (kc + 1 < KC) {
            issue_chunk(kc + 1);
            asm volatile("cp.async.wait_group 1;" ::: "memory");
        } else {
            asm volatile("cp.async.wait_group 0;" ::: "memory");
        }
        __syncthreads();

        const uint32_t tb = sb + SMEM_TILES + (kc & 1) * 65536;
#pragma unroll
        for (int ks = 0; ks < 4; ks++) {
            uint32_t ah[4][4], al[4][4], bh[4][2], bl[4][2];
#pragma unroll
            for (int mi = 0; mi < 4; mi++) {
                const uint32_t off = SWZ((uint32_t)((arow + mi * 16) << 7) + ks * 32 + akb);
                ldsm_x4(ah[mi], tb + off);
                ldsm_x4(al[mi], tb + 16384 + off);
            }
#pragma unroll
            for (int ni = 0; ni < 4; ni++) {
                const uint32_t off = SWZ((uint32_t)((brow + ni * 8) << 7) + ks * 32 + bkb);
                ldsm_x2(bh[ni], tb + 32768 + off);
                ldsm_x2(bl[ni], tb + 49152 + off);
            }
#pragma unroll
            for (int mi = 0; mi < 4; mi++)
#pragma unroll
                for (int ni = 0; ni < 4; ni++) {
                    mma16816(acc[mi][ni], ah[mi], bh[ni]);
                    mma16816(acc[mi][ni], ah[mi], bl[ni]);
                    mma16816(acc[mi][ni], al[mi], bh[ni]);
                }
        }
        __syncthreads();
    }

    const int lr  = lid >> 2;
    const int lc2 = (lid & 3) * 2;
#pragma unroll
    for (int mi = 0; mi < 4; mi++) {
        const long long m0 = bm + wm + mi * 16 + lr;
#pragma unroll
        for (int ni = 0; ni < 4; ni++) {
            const int col = bn + wn + ni * 8 + lc2;
            const float b0 = bias ? bias[col] : 0.f;
            const float b1 = bias ? bias[col + 1] : 0.f;
            const float v00 = acc[mi][ni][0] * scale + b0;
            const float v01 = acc[mi][ni][1] * scale + b1;
            const float v10 = acc[mi][ni][2] * scale + b0;
            const float v11 = acc[mi][ni][3] * scale + b1;
            if (OUTM == 0) {
                *reinterpret_cast<float2*>(Cf + coff + m0 * ldc + col) =
                    make_float2(v00, v01);
                *reinterpret_cast<float2*>(Cf + coff + (m0 + 8) * ldc + col) =
                    make_float2(v10, v11);
            } else {
                uint32_t h0, l0, h1, l1;
                packsplit(v00, v01, h0, l0);
                packsplit(v10, v11, h1, l1);
                *reinterpret_cast<uint32_t*>(Chi + coff + m0 * ldc + col) = h0;
                *reinterpret_cast<uint32_t*>(Clo + coff + m0 * ldc + col) = l0;
                *reinterpret_cast<uint32_t*>(Chi + coff + (m0 + 8) * ldc + col) = h1;
                *reinterpret_cast<uint32_t*>(Clo + coff + (m0 + 8) * ldc + col) = l1;
            }
        }
    }
}

// ---------------- fused flash attention, Bc=64, fragment-preloaded ----------------
// grid (SEQ/128, BSZ*NH), 256 threads, 1 CTA/SM (192KB smem).
// smem: Q 64KB | K 2x32KB | V 2x32KB.
#define FL_SMEM (3 * 65536)

// Q tile: 128 rows x 128 cols hi+lo. blocks: hi c0-63 @0, hi c64-127 @16384,
// lo @32768, @49152.
__device__ __forceinline__ void fl_load_q(uint32_t sm, const bf16* gh,
                                          const bf16* gl, int tid)
{
    const int r = tid >> 3, seg = tid & 7;
#pragma unroll
    for (int i = 0; i < 4; i++) {
        const int row = r + i * 32;
        const uint32_t sw = SWZ((row << 7) + (seg << 4));
        const long long go = (long long)row * 2048 + seg * 8;
        cpasync16(sm + sw,         gh + go);
        cpasync16(sm + 16384 + sw, gh + go + 64);
        cpasync16(sm + 32768 + sw, gl + go);
        cpasync16(sm + 49152 + sw, gl + go + 64);
    }
}

// K tile: 64 rows x 128 cols hi+lo. hi blk0 @0, hi blk1 @8192, lo @16384, @24576.
__device__ __forceinline__ void fl_load_k(uint32_t sm, const bf16* gh,
                                          const bf16* gl, int tid)
{
    const int r = tid >> 3, seg = tid & 7;
#pragma unroll
    for (int i = 0; i < 2; i++) {
        const int row = r + i * 32;
        const uint32_t sw = SWZ((row << 7) + (seg << 4));
        const long long go = (long long)row * 2048 + seg * 8;
        cpasync16(sm + sw,         gh + go);
        cpasync16(sm + 8192 + sw,  gh + go + 64);
        cpasync16(sm + 16384 + sw, gl + go);
        cpasync16(sm + 24576 + sw, gl + go + 64);
    }
}

// V tile: 128 d-rows x 64 s-cols hi+lo (vt layout [d, SEQ]). hi @0, lo @16384.
__device__ __forceinline__ void fl_load_v(uint32_t sm, const bf16* gh,
                                          const bf16* gl, int tid)
{
    const int r = tid >> 3, seg = tid & 7;
#pragma unroll
    for (int i = 0; i < 4; i++) {
        const int row = r + i * 32;
        const uint32_t sw = SWZ((row << 7) + (seg << 4));
        const long long go = (long long)row * 2048 + seg * 8;
        cpasync16(sm + sw,         gh + go);
        cpasync16(sm + 16384 + sw, gl + go);
    }
}

__global__ __launch_bounds__(256, 1)
void flash_kernel(const bf16* __restrict__ Qhi, const bf16* __restrict__ Qlo,
                  const bf16* __restrict__ Khi, const bf16* __restrict__ Klo,
                  const bf16* __restrict__ Vthi, const bf16* __restrict__ Vtlo,
                  bf16* __restrict__ Ahi, bf16* __restrict__ Alo)
{
    extern __shared__ char smem[];
    const uint32_t sb = smem_u32(smem);
    const uint32_t sQ = sb, sK = sb + 65536, sV = sb + 131072;

    const int tid = threadIdx.x;
    const int wid = tid >> 5, lid = tid & 31;
    const int bh = blockIdx.y, b = bh >> 4, h = bh & 15;
    const int q0 = blockIdx.x * 128;

    const bf16* qh = Qhi + (long long)(b * SEQ + q0) * 2048 + h * 128;
    const bf16* ql = Qlo + (long long)(b * SEQ + q0) * 2048 + h * 128;
    const bf16* kh = Khi + (long long)(b * SEQ) * 2048 + h * 128;
    const bf16* kl = Klo + (long long)(b * SEQ) * 2048 + h * 128;
    const bf16* vh = Vthi + (long long)bh * 128 * 2048;
    const bf16* vl = Vtlo + (long long)bh * 128 * 2048;

    // prologue: G1={Q,K0}, G2={V0}
    fl_load_q(sQ, qh, ql, tid);
    fl_load_k(sK, kh, kl, tid);
    asm volatile("cp.async.commit_group;" ::: "memory");
    fl_load_v(sV, vh, vl, tid);
    asm volatile("cp.async.commit_group;" ::: "memory");

    float o[16][4];
#pragma unroll
    for (int t = 0; t < 16; t++)
#pragma unroll
        for (int c = 0; c < 4; c++) o[t][c] = 0.f;
    float m0 = -1e30f, m1 = -1e30f, l0 = 0.f, l1 = 0.f;

    const float SC = 1.4426950408889634f * 0.08838834764831845f;  // log2(e)/sqrt(HD)

    const int arow = wid * 16 + (lid & 15);
    const uint32_t akb = (lid >> 4) * 16;
    const int brow8 = lid & 7;
    const uint32_t bkb = ((lid >> 3) & 1) * 16;

    const int NIT = SEQ / 64;  // 32

    for (int j = 0; j < NIT; j++) {
        asm volatile("cp.async.wait_group 1;" ::: "memory");  // K_j ready
        __syncthreads();

        // prefetch K_{j+1} into the other buffer (its last reader was iter j-1)
        if (j + 1 < NIT)
            fl_load_k(sK + ((j + 1) & 1) * 32768,
                      kh + (long long)(j + 1) * 64 * 2048,
                      kl + (long long)(j + 1) * 64 * 2048, tid);
        asm volatile("cp.async.commit_group;" ::: "memory");

        // ---- S = Q K^T (3-term), fragments preloaded per k-slab ----
        const uint32_t kb = sK + (j & 1) * 32768;
        float s[8][4];
#pragma unroll
        for (int t = 0; t < 8; t++)
#pragma unroll
            for (int c = 0; c < 4; c++) s[t][c] = 0.f;

#pragma unroll 1
        for (int ks = 0; ks < 8; ks++) {
            const uint32_t qoff =
                SWZ((arow << 7) + (ks & 3) * 32 + akb) + (ks >> 2) * 16384;
            uint32_t qfh[4], qfl[4];
            ldsm_x4(qfh, sQ + qoff);
            ldsm_x4(qfl, sQ + 32768 + qoff);

            uint32_t kfh[8][2], kfl[8][2];
#pragma unroll
            for (int nt = 0; nt < 8; nt++) {
                const uint32_t koff = (ks >> 2) * 8192 +
                    SWZ(((nt * 8 + brow8) << 7) + (ks & 3) * 32 + bkb);
                ldsm_x2(kfh[nt], kb + koff);
                ldsm_x2(kfl[nt], kb + 16384 + koff);
            }
#pragma unroll
            for (int nt = 0; nt < 8; nt++) {
                mma16816(s[nt], qfh, kfh[nt]);
                mma16816(s[nt], qfh, kfl[nt]);
                mma16816(s[nt], qfl, kfh[nt]);
            }
        }

        // ---- online softmax ----
        float tm0 = -1e30f, tm1 = -1e30f;
#pragma unroll
        for (int t = 0; t < 8; t++) {
            s[t][0] *= SC; s[t][1] *= SC; s[t][2] *= SC; s[t][3] *= SC;
            tm0 = fmaxf(tm0, fmaxf(s[t][0], s[t][1]));
            tm1 = fmaxf(tm1, fmaxf(s[t][2], s[t][3]));
        }
        tm0 = fmaxf(tm0, __shfl_xor_sync(0xffffffff, tm0, 1));
        tm0 = fmaxf(tm0, __shfl_xor_sync(0xffffffff, tm0, 2));
        tm1 = fmaxf(tm1, __shfl_xor_sync(0xffffffff, tm1, 1));
        tm1 = fmaxf(tm1, __shfl_xor_sync(0xffffffff, tm1, 2));
        const float mn0 = fmaxf(m0, tm0), mn1 = fmaxf(m1, tm1);
        const float sc0 = exp2f(m0 - mn0), sc1 = exp2f(m1 - mn1);
        m0 = mn0; m1 = mn1;

        float ts0 = 0.f, ts1 = 0.f;
#pragma unroll
        for (int t = 0; t < 8; t++) {
            s[t][0] = exp2f(s[t][0] - m0);
            s[t][1] = exp2f(s[t][1] - m0);
            s[t][2] = exp2f(s[t][2] - m1);
            s[t][3] = exp2f(s[t][3] - m1);
            ts0 += s[t][0] + s[t][1];
            ts1 += s[t][2] + s[t][3];
        }
#pragma unroll
        for (int t = 0; t < 16; t++) {
            o[t][0] *= sc0; o[t][1] *= sc0;
            o[t][2] *= sc1; o[t][3] *= sc1;
        }
        l0 = l0 * sc0 + ts0;
        l1 = l1 * sc1 + ts1;

        asm volatile("cp.async.wait_group 1;" ::: "memory");  // V_j ready
        __syncthreads();

        // prefetch V_{j+1}
        if (j + 1 < NIT)
            fl_load_v(sV + ((j + 1) & 1) * 32768,
                      vh + (long long)(j + 1) * 64,
                      vl + (long long)(j + 1) * 64, tid);
        asm volatile("cp.async.commit_group;" ::: "memory");

        // ---- O += P V^T (3-term), fragments preloaded in two nt-blocks ----
        const uint32_t vb = sV + (j & 1) * 32768;
#pragma unroll 1
        for (int ks = 0; ks < 4; ks++) {
            uint32_t ph[4], pl[4];
            packsplit(s[2 * ks][0],     s[2 * ks][1],     ph[0], pl[0]);
            packsplit(s[2 * ks][2],     s[2 * ks][3],     ph[1], pl[1]);
            packsplit(s[2 * ks + 1][0], s[2 * ks + 1][1], ph[2], pl[2]);
            packsplit(s[2 * ks + 1][2], s[2 * ks + 1][3], ph[3], pl[3]);
#pragma unroll
            for (int blk = 0; blk < 2; blk++) {
                uint32_t vfh[8][2], vfl[8][2];
#pragma unroll
                for (int q8 = 0; q8 < 8; q8++) {
                    const int nt = blk * 8 + q8;
                    const uint32_t voff =
                        SWZ(((nt * 8 + brow8) << 7) + ks * 32 + bkb);
                    ldsm_x2(vfh[q8], vb + voff);
                    ldsm_x2(vfl[q8], vb + 16384 + voff);
                }
#pragma unroll
                for (int q8 = 0; q8 < 8; q8++) {
                    const int nt = blk * 8 + q8;
                    mma16816(o[nt], ph, vfh[q8]);
                    mma16816(o[nt], ph, vfl[q8]);
                    mma16816(o[nt], pl, vfh[q8]);
                }
            }
        }
    }

    // ---- epilogue: normalize and write att hi/lo ----
    l0 += __shfl_xor_sync(0xffffffff, l0, 1);
    l0 += __shfl_xor_sync(0xffffffff, l0, 2);
    l1 += __shfl_xor_sync(0xffffffff, l1, 1);
    l1 += __shfl_xor_sync(0xffffffff, l1, 2);
    const float inv0 = 1.f / l0, inv1 = 1.f / l1;

    const int g = lid >> 2;
    const long long row0 = (long long)(b * SEQ + q0 + wid * 16 + g);
    const long long row1 = row0 + 8;
    const int colb = h * 128 + (lid & 3) * 2;
#pragma unroll
    for (int nt = 0; nt < 16; nt++) {
        const int col = colb + nt * 8;
        uint32_t h0, lo0, h1, lo1;
        packsplit(o[nt][0] * inv0, o[nt][1] * inv0, h0, lo0);
        packsplit(o[nt][2] * inv1, o[nt][3] * inv1, h1, lo1);
        *reinterpret_cast<uint32_t*>(Ahi + row0 * 2048 + col) = h0;
        *reinterpret_cast<uint32_t*>(Alo + row0 * 2048 + col) = lo0;
        *reinterpret_cast<uint32_t*>(Ahi + row1 * 2048 + col) = h1;
        *reinterpret_cast<uint32_t*>(Alo + row1 * 2048 + col) = lo1;
    }
}

// ---------------- elementwise split kernels ----------------
__global__ void split_kernel(const float* __restrict__ in,
                             bf16* __restrict__ hi, bf16* __restrict__ lo,
                             long long n)
{
    const long long i = ((long long)blockIdx.x * blockDim.x + threadIdx.x) * 4;
    if (i >= n) return;
    const float4 v = *reinterpret_cast<const float4*>(in + i);
    alignas(8) bf16 h[4], l[4];
    split2(v.x, h[0], l[0]); split2(v.y, h[1], l[1]);
    split2(v.z, h[2], l[2]); split2(v.w, h[3], l[3]);
    *reinterpret_cast<uint2*>(hi + i) = *reinterpret_cast<const uint2*>(h);
    *reinterpret_cast<uint2*>(lo + i) = *reinterpret_cast<const uint2*>(l);
}

__global__ void ksplit_kernel(const float* __restrict__ kv,
                              bf16* __restrict__ khi, bf16* __restrict__ klo)
{
    const long long i = ((long long)blockIdx.x * blockDim.x + threadIdx.x) * 4;
    if (i >= XN) return;
    const long long row = i >> 11, col = i & 2047;
    const float4 v = *reinterpret_cast<const float4*>(kv + row * 4096 + col);
    alignas(8) bf16 h[4], l[4];
    split2(v.x, h[0], l[0]); split2(v.y, h[1], l[1]);
    split2(v.z, h[2], l[2]); split2(v.w, h[3], l[3]);
    *reinterpret_cast<uint2*>(khi + i) = *reinterpret_cast<const uint2*>(h);
    *reinterpret_cast<uint2*>(klo + i) = *reinterpret_cast<const uint2*>(l);
}

__global__ void vtrans_kernel(const float* __restrict__ kv,
                              bf16* __restrict__ vthi, bf16* __restrict__ vtlo)
{
    __shared__ float t[32][33];
    const int b = blockIdx.z >> 4, h = blockIdx.z & 15;
    const int s0 = blockIdx.x * 32, d0 = blockIdx.y * 32;
    const int tx = threadIdx.x, ty = threadIdx.y;
    t[ty][tx] = kv[(long long)(b * SEQ + s0 + ty) * 4096 + 2048 + h * 128 + d0 + tx];
    __syncthreads();
    const float v = t[tx][ty];
    const long long o = (long long)((b * NH + h) * HD + d0 + ty) * SEQ + s0 + tx;
    bf16 hv, lv;
    split2(v, hv, lv);
    vthi[o] = hv;
    vtlo[o] = lv;
}

// ---------------- host ----------------
static void do_split(const float* in, bf16* hi, bf16* lo, long long n) {
    split_kernel<<<(unsigned)((n / 4 + 255) / 256), 256>>>(in, hi, lo, n);
}

extern "C" void kernel_launch(void* const* d_in, const int* in_sizes, int n_in,
                              void* d_out, int out_size)
{
    const float* x     = (const float*)d_in[0];
    const float* q_w   = (const float*)d_in[1];
    const float* q_b   = (const float*)d_in[2];
    const float* kvd_w = (const float*)d_in[3];
    const float* kvd_b = (const float*)d_in[4];
    const float* kvu_w = (const float*)d_in[5];
    const float* kvu_b = (const float*)d_in[6];
    const float* out_w = (const float*)d_in[7];
    const float* out_b = (const float*)d_in[8];
    float* out = (float*)d_out;

    bf16 *x_hi, *x_lo, *qw_hi, *qw_lo, *kvdw_hi, *kvdw_lo, *kvuw_hi, *kvuw_lo,
         *ow_hi, *ow_lo, *q_hi, *q_lo, *lat_hi, *lat_lo, *k_hi, *k_lo,
         *vt_hi, *vt_lo, *att_hi, *att_lo;
    float *kv;
    cudaGetSymbolAddress((void**)&x_hi, g_x_hi);     cudaGetSymbolAddress((void**)&x_lo, g_x_lo);
    cudaGetSymbolAddress((void**)&qw_hi, g_qw_hi);   cudaGetSymbolAddress((void**)&qw_lo, g_qw_lo);
    cudaGetSymbolAddress((void**)&kvdw_hi, g_kvdw_hi); cudaGetSymbolAddress((void**)&kvdw_lo, g_kvdw_lo);
    cudaGetSymbolAddress((void**)&kvuw_hi, g_kvuw_hi); cudaGetSymbolAddress((void**)&kvuw_lo, g_kvuw_lo);
    cudaGetSymbolAddress((void**)&ow_hi, g_ow_hi);   cudaGetSymbolAddress((void**)&ow_lo, g_ow_lo);
    cudaGetSymbolAddress((void**)&q_hi, g_q_hi);     cudaGetSymbolAddress((void**)&q_lo, g_q_lo);
    cudaGetSymbolAddress((void**)&lat_hi, g_lat_hi); cudaGetSymbolAddress((void**)&lat_lo, g_lat_lo);
    cudaGetSymbolAddress((void**)&k_hi, g_k_hi);     cudaGetSymbolAddress((void**)&k_lo, g_k_lo);
    cudaGetSymbolAddress((void**)&vt_hi, g_vt_hi);   cudaGetSymbolAddress((void**)&vt_lo, g_vt_lo);
    cudaGetSymbolAddress((void**)&att_hi, g_att_hi); cudaGetSymbolAddress((void**)&att_lo, g_att_lo);
    cudaGetSymbolAddress((void**)&kv, g_kv);

    cudaFuncSetAttribute(tgemm<0>, cudaFuncAttributeMaxDynamicSharedMemorySize, SMEM_BYTES);
    cudaFuncSetAttribute(tgemm<1>, cudaFuncAttributeMaxDynamicSharedMemorySize, SMEM_BYTES);
    cudaFuncSetAttribute(flash_kernel, cudaFuncAttributeMaxDynamicSharedMemorySize, FL_SMEM);

    do_split(x,     x_hi,    x_lo,    XN);
    do_split(q_w,   qw_hi,   qw_lo,   (long long)EMBED * EMBED);
    do_split(kvd_w, kvdw_hi, kvdw_lo, (long long)LATENT * EMBED);
    do_split(kvu_w, kvuw_hi, kvuw_lo, (long long)2 * EMBED * LATENT);
    do_split(out_w, ow_hi,   ow_lo,   (long long)EMBED * EMBED);

    const int M = BSZ * SEQ;  // 4096

    // 1) q = x @ q_w^T + q_b -> hi/lo planes
    tgemm<1><<<dim3(EMBED / 128, M / 128, 1), 256, SMEM_BYTES>>>(
        x_hi, x_lo, EMBED, qw_hi, qw_lo, EMBED, q_b, 1.f,
        nullptr, q_hi, q_lo, EMBED, EMBED, 1, 0, 0, 0, 0, 0, 0);

    // 2) latent = x @ kvd_w^T + kvd_b -> hi/lo
    tgemm<1><<<dim3(LATENT / 128, M / 128, 1), 256, SMEM_BYTES>>>(
        x_hi, x_lo, EMBED, kvdw_hi, kvdw_lo, EMBED, kvd_b, 1.f,
        nullptr, lat_hi, lat_lo, LATENT, EMBED, 1, 0, 0, 0, 0, 0, 0);

    // 3) kv = latent @ kvu_w^T + kvu_b -> fp32
    tgemm<0><<<dim3(2 * EMBED / 128, M / 128, 1), 256, SMEM_BYTES>>>(
        lat_hi, lat_lo, LATENT, kvuw_hi, kvuw_lo, LATENT, kvu_b, 1.f,
        kv, nullptr, nullptr, 2 * EMBED, LATENT, 1, 0, 0, 0, 0, 0, 0);

    // 4) k split + v transpose-split
    ksplit_kernel<<<(unsigned)(XN / 4 / 256), 256>>>(kv, k_hi, k_lo);
    vtrans_kernel<<<dim3(SEQ / 32, HD / 32, BSZ * NH), dim3(32, 32)>>>(kv, vt_hi, vt_lo);

    // 5-7) fused flash attention -> att hi/lo
    flash_kernel<<<dim3(SEQ / 128, BSZ * NH), 256, FL_SMEM>>>(
        q_hi, q_lo, k_hi, k_lo, vt_hi, vt_lo, att_hi, att_lo);

    // 8) out = att @ out_w^T + out_b -> fp32 (d_out)
    tgemm<0><<<dim3(EMBED / 128, M / 128, 1), 256, SMEM_BYTES>>>(
        att_hi, att_lo, EMBED, ow_hi, ow_lo, EMBED, out_b, 1.f,
        out, nullptr, nullptr, EMBED, EMBED, 1, 0, 0, 0, 0, 0, 0);
}